// round 14
// baseline (speedup 1.0000x reference)
#include <cuda_runtime.h>

// ---------------- problem constants ----------------
#define Bn   4
#define Cc   64
#define DWc  128
#define Hh   256
#define Ww   256
#define HWp  65536            // H*W
#define EPSv 1e-6f
#define SCAL 2.0f

typedef unsigned long long u64;

// ---------------- packed f32x2 helpers (sm_103a FFMA2 path) ----------------
__device__ __forceinline__ u64 splat2(float w) {
    u64 r; unsigned int wi = __float_as_uint(w);
    asm("mov.b64 %0, {%1, %1};" : "=l"(r) : "r"(wi));
    return r;
}
__device__ __forceinline__ void ffma2(u64& d, u64 a, u64 b) {
    asm("fma.rn.f32x2 %0, %1, %2, %0;" : "+l"(d) : "l"(a), "l"(b));
}
__device__ __forceinline__ u64 add2(u64 a, u64 b) {
    u64 r; asm("add.rn.f32x2 %0, %1, %2;" : "=l"(r) : "l"(a), "l"(b)); return r;
}
__device__ __forceinline__ u64 mul2(u64 a, u64 b) {
    u64 r; asm("mul.rn.f32x2 %0, %1, %2;" : "=l"(r) : "l"(a), "l"(b)); return r;
}
__device__ __forceinline__ float2 unpack2(u64 v) {
    unsigned lo, hi;
    asm("mov.b64 {%0, %1}, %2;" : "=r"(lo), "=r"(hi) : "l"(v));
    float2 f; f.x = __uint_as_float(lo); f.y = __uint_as_float(hi);
    return f;
}

// ---------------- device scratch (no cudaMalloc allowed) ----------------
__device__ float g_w1  [Bn * DWc * Cc];
__device__ float g_w2  [Bn * DWc * 9];
__device__ float g_wsca[Bn * Cc * Cc];
__device__ float g_w3  [Bn * Cc * Cc];
__device__ float g_w4  [Bn * DWc * Cc];
__device__ float g_w5  [Bn * Cc * Cc];
__device__ float g_t1  [Bn * DWc * HWp];    // conv1 out
__device__ float g_xg  [Bn * Cc  * HWp];    // after simple_gate
__device__ float g_part[Bn * Cc * 64];      // deterministic pool partials

// ---------------- K0: gate + effective weights ----------------
__device__ __forceinline__ void mix1x1(const float* w, const float* la, const float* lb,
                                       float* dst, int O, int e, float gs, int t) {
    const float* lae = la + e * 4 * 64;
    int N = O * 64;
    for (int idx = t; idx < N; idx += 256) {
        int o = idx >> 6, i = idx & 63;
        const float* lbo = lb + (e * O + o) * 4;
        dst[idx] = w[idx] + gs * (lbo[0] * lae[i] + lbo[1] * lae[64 + i] +
                                  lbo[2] * lae[128 + i] + lbo[3] * lae[192 + i]);
    }
}

__global__ void k_weights(const float* __restrict__ probs,
                          const float* w1, const float* la1, const float* lb1,
                          const float* w2, const float* la2, const float* lb2,
                          const float* wsca, const float* lasca, const float* lbsca,
                          const float* w3, const float* la3, const float* lb3,
                          const float* w4, const float* la4, const float* lb4,
                          const float* w5, const float* la5, const float* lb5) {
    int b = blockIdx.y, job = blockIdx.x, t = threadIdx.x;
    float p0 = probs[b * 3 + 0], p1 = probs[b * 3 + 1], p2 = probs[b * 3 + 2];
    int e = 0; float g = p0;
    if (p1 > g) { g = p1; e = 1; }
    if (p2 > g) { g = p2; e = 2; }
    float gs = g * SCAL;

    if (job == 0) {
        mix1x1(w1, la1, lb1, g_w1 + b * DWc * Cc, DWc, e, gs, t);
    } else if (job == 1) {
        for (int idx = t; idx < DWc * 9; idx += 256) {
            int row = idx / 3, col = idx - row * 3;
            const float* lbo = lb2 + (e * 384 + row) * 12;
            const float* lae = la2 + e * 36 + col;
            float acc = w2[idx];
            #pragma unroll
            for (int r = 0; r < 12; ++r) acc += gs * lbo[r] * lae[r * 3];
            g_w2[b * DWc * 9 + idx] = acc;
        }
    } else if (job == 2) {
        mix1x1(wsca, lasca, lbsca, g_wsca + b * Cc * Cc, Cc, e, gs, t);
    } else if (job == 3) {
        mix1x1(w3, la3, lb3, g_w3 + b * Cc * Cc, Cc, e, gs, t);
    } else if (job == 4) {
        mix1x1(w4, la4, lb4, g_w4 + b * DWc * Cc, DWc, e, gs, t);
    } else {
        mix1x1(w5, la5, lb5, g_w5 + b * Cc * Cc, Cc, e, gs, t);
    }
}

// warp-local remap: 4 ocg x 8 pxg per warp -> LDS.128 x-loads dedup to 1 wavefront
__device__ __forceinline__ void remap_ocg_pxg(int t, int& ocg, int& pxg) {
    int w = t >> 5, lane = t & 31;
    ocg = ((w >> 1) << 2) | (lane >> 3);   // 0..15
    pxg = ((w & 1) << 3) | (lane & 7);     // 0..15
}

// ---------------- K1: LN1 + conv1 (1x1, 64->128) ----------------
// grid (512, B), block 256.  Tile = 128 px.  Thread: 8 oc x 8 px ({px0..+3, px0+64..+67}).
// Weights straight from gmem (L1-cached broadcast float4); x in smem stride 132.
#define XS1 132
__global__ void __launch_bounds__(256, 2)
k1_kernel(const float* __restrict__ inp,
          const float* __restrict__ ln1w, const float* __restrict__ ln1b,
          const float* __restrict__ b1) {
    __shared__ float xs[64 * XS1];
    __shared__ float sred[256], qred[256], smean[128], sinv[128];
    __shared__ float lnws[64], lnbs[64];

    int b = blockIdx.y;
    int pix0 = blockIdx.x * 128;
    int t = threadIdx.x;

    if (t < 64) { lnws[t] = ln1w[t]; lnbs[t] = ln1b[t]; }

    const float* ib = inp + b * Cc * HWp + pix0;
    #pragma unroll
    for (int it = 0; it < 32; ++it) {
        int idx = it * 256 + t;
        int c = idx >> 7, p = idx & 127;
        xs[c * XS1 + p] = ib[c * HWp + p];
    }
    __syncthreads();

    // LN1 (conflict-free): thread -> pixel p = t&127, half hh = t>>7 (32 channels)
    {
        int p = t & 127, hh = t >> 7;
        float s = 0.f, qs = 0.f;
        #pragma unroll
        for (int c = 0; c < 32; ++c) {
            float v = xs[(hh * 32 + c) * XS1 + p];
            s += v; qs += v * v;
        }
        sred[t] = s; qred[t] = qs;
        __syncthreads();
        if (t < 128) {
            float S = sred[t] + sred[t + 128];
            float Q = qred[t] + qred[t + 128];
            float mean = S * (1.f / 64.f);
            float var  = Q * (1.f / 64.f) - mean * mean;
            smean[t] = mean;
            sinv[t]  = rsqrtf(var + EPSv);
        }
        __syncthreads();
        float mean = smean[p], inv = sinv[p];
        #pragma unroll
        for (int c = 0; c < 32; ++c) {
            int ch = hh * 32 + c;
            float v = xs[ch * XS1 + p];
            xs[ch * XS1 + p] = (v - mean) * inv * lnws[ch] + lnbs[ch];
        }
    }
    __syncthreads();

    // GEMM: 128 oc x 128 px, K=64.  Thread: 8 oc x 8 px.  Weights via __ldg float4.
    int ocg, pxg; remap_ocg_pxg(t, ocg, pxg);
    int oc0 = ocg * 8, px0 = pxg * 4;
    const float* wb = g_w1 + b * DWc * Cc;
    u64 acc[8][4];
    #pragma unroll
    for (int u = 0; u < 8; ++u)
        #pragma unroll
        for (int v = 0; v < 4; ++v) acc[u][v] = 0ull;

    for (int kc = 0; kc < 64; kc += 4) {
        ulonglong2 xA0 = *(const ulonglong2*)(xs + (kc + 0) * XS1 + px0);
        ulonglong2 xB0 = *(const ulonglong2*)(xs + (kc + 0) * XS1 + px0 + 64);
        ulonglong2 xA1 = *(const ulonglong2*)(xs + (kc + 1) * XS1 + px0);
        ulonglong2 xB1 = *(const ulonglong2*)(xs + (kc + 1) * XS1 + px0 + 64);
        ulonglong2 xA2 = *(const ulonglong2*)(xs + (kc + 2) * XS1 + px0);
        ulonglong2 xB2 = *(const ulonglong2*)(xs + (kc + 2) * XS1 + px0 + 64);
        ulonglong2 xA3 = *(const ulonglong2*)(xs + (kc + 3) * XS1 + px0);
        ulonglong2 xB3 = *(const ulonglong2*)(xs + (kc + 3) * XS1 + px0 + 64);
        #pragma unroll
        for (int u = 0; u < 8; ++u) {
            float4 wv = __ldg((const float4*)(wb + (oc0 + u) * Cc + kc));
            u64 w0 = splat2(wv.x), w1s = splat2(wv.y);
            u64 w2s = splat2(wv.z), w3s = splat2(wv.w);
            ffma2(acc[u][0], w0, xA0.x);  ffma2(acc[u][1], w0, xA0.y);
            ffma2(acc[u][2], w0, xB0.x);  ffma2(acc[u][3], w0, xB0.y);
            ffma2(acc[u][0], w1s, xA1.x); ffma2(acc[u][1], w1s, xA1.y);
            ffma2(acc[u][2], w1s, xB1.x); ffma2(acc[u][3], w1s, xB1.y);
            ffma2(acc[u][0], w2s, xA2.x); ffma2(acc[u][1], w2s, xA2.y);
            ffma2(acc[u][2], w2s, xB2.x); ffma2(acc[u][3], w2s, xB2.y);
            ffma2(acc[u][0], w3s, xA3.x); ffma2(acc[u][1], w3s, xA3.y);
            ffma2(acc[u][2], w3s, xB3.x); ffma2(acc[u][3], w3s, xB3.y);
        }
    }

    float* ob = g_t1 + b * DWc * HWp + pix0 + px0;
    #pragma unroll
    for (int u = 0; u < 8; ++u) {
        float bias = __ldg(&b1[oc0 + u]);
        float2 p0 = unpack2(acc[u][0]), p1 = unpack2(acc[u][1]);
        float2 p2 = unpack2(acc[u][2]), p3 = unpack2(acc[u][3]);
        float4 r0 = make_float4(p0.x + bias, p0.y + bias, p1.x + bias, p1.y + bias);
        float4 r1 = make_float4(p2.x + bias, p2.y + bias, p3.x + bias, p3.y + bias);
        *(float4*)(ob + (oc0 + u) * HWp)      = r0;
        *(float4*)(ob + (oc0 + u) * HWp + 64) = r1;
    }
}

// ---------------- K2: depthwise 3x3 + simple_gate + pool partials ----------------
__global__ void k2_kernel(const float* __restrict__ b2) {
    __shared__ float s0[6][256];
    __shared__ float s1[6][256];
    __shared__ float red[256];

    int b = blockIdx.z, c = blockIdx.y;
    int r0 = blockIdx.x * 4;
    int t = threadIdx.x;

    const float* t1a = g_t1 + (b * DWc + c) * HWp;
    const float* t1b = g_t1 + (b * DWc + c + 64) * HWp;

    #pragma unroll
    for (int lr = 0; lr < 6; ++lr) {
        int gr = r0 + lr - 1;
        bool ok = (gr >= 0 && gr < Hh);
        s0[lr][t] = ok ? t1a[gr * Ww + t] : 0.f;
        s1[lr][t] = ok ? t1b[gr * Ww + t] : 0.f;
    }
    __syncthreads();

    float wa[9], wb9[9];
    const float* w2a = g_w2 + (b * DWc + c) * 9;
    const float* w2b = g_w2 + (b * DWc + c + 64) * 9;
    #pragma unroll
    for (int i = 0; i < 9; ++i) { wa[i] = __ldg(&w2a[i]); wb9[i] = __ldg(&w2b[i]); }
    float biasA = __ldg(&b2[c]), biasB = __ldg(&b2[c + 64]);

    float* xgp = g_xg + (b * Cc + c) * HWp;
    float lsum = 0.f;
    int w = t;
    #pragma unroll
    for (int j = 0; j < 4; ++j) {
        float a0 = biasA, a1 = biasB;
        #pragma unroll
        for (int kh = 0; kh < 3; ++kh) {
            #pragma unroll
            for (int kw = 0; kw < 3; ++kw) {
                int col = w + kw - 1;
                bool ok = (col >= 0 && col < Ww);
                float v0 = ok ? s0[j + kh][col] : 0.f;
                float v1 = ok ? s1[j + kh][col] : 0.f;
                a0 += wa[kh * 3 + kw] * v0;
                a1 += wb9[kh * 3 + kw] * v1;
            }
        }
        float val = a0 * a1;
        xgp[(r0 + j) * Ww + w] = val;
        lsum += val;
    }

    red[t] = lsum;
    __syncthreads();
    #pragma unroll
    for (int o = 128; o > 0; o >>= 1) {
        if (t < o) red[t] += red[t + o];
        __syncthreads();
    }
    if (t == 0) g_part[(b * Cc + c) * 64 + blockIdx.x] = red[0];
}

// ---------------- K4: fused per-pixel tail ----------------
// grid (512, B), block 256.  Tile = 128 px, thread = 8 px ({px0..+3, px0+64..+67}).
// Pixel buffers in dynamic smem (stride 132); weights via gmem L1-cached float4.
#define PS4 132
__global__ void __launch_bounds__(256, 2)
k4_kernel(const float* __restrict__ inp,
          const float* __restrict__ ln2w, const float* __restrict__ ln2b,
          const float* __restrict__ bsca,
          const float* __restrict__ b3, const float* __restrict__ b4,
          const float* __restrict__ b5,
          const float* __restrict__ beta, const float* __restrict__ gamma,
          float* __restrict__ out) {
    extern __shared__ float sm[];
    float* xsb = sm;                   // 64*132 (x, then LN2 output)
    float* ysb = xsb + 64 * PS4;       // 64*132 (residual y)
    float* gsb = ysb + 64 * PS4;       // 64*132 (gate output)
    __shared__ float sred[256], qred[256], smean[128], sinv[128];
    __shared__ float lnws[64], lnbs[64];
    __shared__ float s_pool[64], s_sca[64];

    int b = blockIdx.y;
    int pix0 = blockIdx.x * 128;
    int t = threadIdx.x;

    if (t < 64) { lnws[t] = ln2w[t]; lnbs[t] = ln2b[t]; }
    // pool mean from partials (k3 fold)
    if (t < 64) {
        float s = 0.f;
        const float4* pp = (const float4*)(g_part + (b * Cc + t) * 64);
        #pragma unroll
        for (int k = 0; k < 16; ++k) {
            float4 v = pp[k];
            s += (v.x + v.y) + (v.z + v.w);
        }
        s_pool[t] = s * (1.f / (float)HWp);
    }
    __syncthreads();
    if (t < 64) {
        const float* wr = g_wsca + b * Cc * Cc + t * Cc;
        float acc = __ldg(&bsca[t]);
        #pragma unroll
        for (int i = 0; i < 64; ++i) acc += wr[i] * s_pool[i];
        s_sca[t] = acc;
    }
    __syncthreads();

    const float* xgb = g_xg + b * Cc * HWp + pix0;
    const float* ib  = inp  + b * Cc * HWp + pix0;
    #pragma unroll
    for (int it = 0; it < 32; ++it) {
        int idx = it * 256 + t;
        int c = idx >> 7, p = idx & 127;
        float sc = s_sca[c];
        xsb[c * PS4 + p] = xgb[c * HWp + p] * sc;
        ysb[c * PS4 + p] = ib[c * HWp + p];
    }
    __syncthreads();

    int ocg, pxg; remap_ocg_pxg(t, ocg, pxg);
    int tg = ocg, px0 = pxg * 4;
    const float* wb3 = g_w3 + b * Cc * Cc;
    const float* wb4 = g_w4 + b * DWc * Cc;
    const float* wb5 = g_w5 + b * Cc * Cc;

    // matvec1: conv3 (64x64); thread 4 oc x 8 px.  y = inp + (t3+bias)*beta
    {
        int oc0 = tg * 4;
        u64 a1[4][4];
        #pragma unroll
        for (int u = 0; u < 4; ++u)
            #pragma unroll
            for (int v = 0; v < 4; ++v) a1[u][v] = 0ull;
        for (int kc = 0; kc < 64; kc += 4) {
            ulonglong2 xA0 = *(const ulonglong2*)(xsb + (kc + 0) * PS4 + px0);
            ulonglong2 xB0 = *(const ulonglong2*)(xsb + (kc + 0) * PS4 + px0 + 64);
            ulonglong2 xA1 = *(const ulonglong2*)(xsb + (kc + 1) * PS4 + px0);
            ulonglong2 xB1 = *(const ulonglong2*)(xsb + (kc + 1) * PS4 + px0 + 64);
            ulonglong2 xA2 = *(const ulonglong2*)(xsb + (kc + 2) * PS4 + px0);
            ulonglong2 xB2 = *(const ulonglong2*)(xsb + (kc + 2) * PS4 + px0 + 64);
            ulonglong2 xA3 = *(const ulonglong2*)(xsb + (kc + 3) * PS4 + px0);
            ulonglong2 xB3 = *(const ulonglong2*)(xsb + (kc + 3) * PS4 + px0 + 64);
            #pragma unroll
            for (int u = 0; u < 4; ++u) {
                float4 wv = __ldg((const float4*)(wb3 + (oc0 + u) * Cc + kc));
                u64 w0 = splat2(wv.x), w1s = splat2(wv.y);
                u64 w2s = splat2(wv.z), w3s = splat2(wv.w);
                ffma2(a1[u][0], w0, xA0.x);  ffma2(a1[u][1], w0, xA0.y);
                ffma2(a1[u][2], w0, xB0.x);  ffma2(a1[u][3], w0, xB0.y);
                ffma2(a1[u][0], w1s, xA1.x); ffma2(a1[u][1], w1s, xA1.y);
                ffma2(a1[u][2], w1s, xB1.x); ffma2(a1[u][3], w1s, xB1.y);
                ffma2(a1[u][0], w2s, xA2.x); ffma2(a1[u][1], w2s, xA2.y);
                ffma2(a1[u][2], w2s, xB2.x); ffma2(a1[u][3], w2s, xB2.y);
                ffma2(a1[u][0], w3s, xA3.x); ffma2(a1[u][1], w3s, xA3.y);
                ffma2(a1[u][2], w3s, xB3.x); ffma2(a1[u][3], w3s, xB3.y);
            }
        }
        #pragma unroll
        for (int u = 0; u < 4; ++u) {
            int o = oc0 + u;
            float bt = __ldg(&beta[o]);
            float bias = __ldg(&b3[o]);
            float2 p0 = unpack2(a1[u][0]), p1 = unpack2(a1[u][1]);
            float2 p2 = unpack2(a1[u][2]), p3 = unpack2(a1[u][3]);
            float4* yv0 = (float4*)(ysb + o * PS4 + px0);
            float4 y0 = *yv0;
            y0.x += (p0.x + bias) * bt;
            y0.y += (p0.y + bias) * bt;
            y0.z += (p1.x + bias) * bt;
            y0.w += (p1.y + bias) * bt;
            *yv0 = y0;
            float4* yv1 = (float4*)(ysb + o * PS4 + px0 + 64);
            float4 y1 = *yv1;
            y1.x += (p2.x + bias) * bt;
            y1.y += (p2.y + bias) * bt;
            y1.z += (p3.x + bias) * bt;
            y1.w += (p3.y + bias) * bt;
            *yv1 = y1;
        }
    }
    __syncthreads();

    // LN2 (conflict-free): thread -> pixel p = t&127, half hh = t>>7 (32 channels).
    // Output -> xsb (dead after matvec1).
    {
        int p = t & 127, hh = t >> 7;
        float s = 0.f, qs = 0.f;
        #pragma unroll
        for (int c = 0; c < 32; ++c) {
            float v = ysb[(hh * 32 + c) * PS4 + p];
            s += v; qs += v * v;
        }
        sred[t] = s; qred[t] = qs;
        __syncthreads();
        if (t < 128) {
            float S = sred[t] + sred[t + 128];
            float Q = qred[t] + qred[t + 128];
            float mean = S * (1.f / 64.f);
            float var  = Q * (1.f / 64.f) - mean * mean;
            smean[t] = mean;
            sinv[t]  = rsqrtf(var + EPSv);
        }
        __syncthreads();
        float mean = smean[p], inv = sinv[p];
        #pragma unroll
        for (int c = 0; c < 32; ++c) {
            int ch = hh * 32 + c;
            float v = ysb[ch * PS4 + p];
            xsb[ch * PS4 + p] = (v - mean) * inv * lnws[ch] + lnbs[ch];
        }
    }
    __syncthreads();

    // matvec2: conv4 (128x64) + simple_gate. oc = tg + 16*j keeps gate pairs in-thread.
    {
        u64 a2[8][4];
        #pragma unroll
        for (int j = 0; j < 8; ++j)
            #pragma unroll
            for (int v = 0; v < 4; ++v) a2[j][v] = 0ull;
        for (int kc = 0; kc < 64; kc += 4) {
            ulonglong2 zA0 = *(const ulonglong2*)(xsb + (kc + 0) * PS4 + px0);
            ulonglong2 zB0 = *(const ulonglong2*)(xsb + (kc + 0) * PS4 + px0 + 64);
            ulonglong2 zA1 = *(const ulonglong2*)(xsb + (kc + 1) * PS4 + px0);
            ulonglong2 zB1 = *(const ulonglong2*)(xsb + (kc + 1) * PS4 + px0 + 64);
            ulonglong2 zA2 = *(const ulonglong2*)(xsb + (kc + 2) * PS4 + px0);
            ulonglong2 zB2 = *(const ulonglong2*)(xsb + (kc + 2) * PS4 + px0 + 64);
            ulonglong2 zA3 = *(const ulonglong2*)(xsb + (kc + 3) * PS4 + px0);
            ulonglong2 zB3 = *(const ulonglong2*)(xsb + (kc + 3) * PS4 + px0 + 64);
            #pragma unroll
            for (int j = 0; j < 8; ++j) {
                float4 wv = __ldg((const float4*)(wb4 + (tg + 16 * j) * Cc + kc));
                u64 w0 = splat2(wv.x), w1s = splat2(wv.y);
                u64 w2s = splat2(wv.z), w3s = splat2(wv.w);
                ffma2(a2[j][0], w0, zA0.x);  ffma2(a2[j][1], w0, zA0.y);
                ffma2(a2[j][2], w0, zB0.x);  ffma2(a2[j][3], w0, zB0.y);
                ffma2(a2[j][0], w1s, zA1.x); ffma2(a2[j][1], w1s, zA1.y);
                ffma2(a2[j][2], w1s, zB1.x); ffma2(a2[j][3], w1s, zB1.y);
                ffma2(a2[j][0], w2s, zA2.x); ffma2(a2[j][1], w2s, zA2.y);
                ffma2(a2[j][2], w2s, zB2.x); ffma2(a2[j][3], w2s, zB2.y);
                ffma2(a2[j][0], w3s, zA3.x); ffma2(a2[j][1], w3s, zA3.y);
                ffma2(a2[j][2], w3s, zB3.x); ffma2(a2[j][3], w3s, zB3.y);
            }
        }
        #pragma unroll
        for (int j = 0; j < 4; ++j) {
            int o = tg + 16 * j;
            u64 bl = splat2(__ldg(&b4[o]));
            u64 bh = splat2(__ldg(&b4[o + 64]));
            ulonglong2 gv0, gv1;
            gv0.x = mul2(add2(a2[j][0], bl), add2(a2[j + 4][0], bh));
            gv0.y = mul2(add2(a2[j][1], bl), add2(a2[j + 4][1], bh));
            gv1.x = mul2(add2(a2[j][2], bl), add2(a2[j + 4][2], bh));
            gv1.y = mul2(add2(a2[j][3], bl), add2(a2[j + 4][3], bh));
            *(ulonglong2*)(gsb + o * PS4 + px0)      = gv0;
            *(ulonglong2*)(gsb + o * PS4 + px0 + 64) = gv1;
        }
    }
    __syncthreads();

    // matvec3: conv5 (64x64);  out = y + (t5+bias)*gamma
    {
        int oc0 = tg * 4;
        u64 a3[4][4];
        #pragma unroll
        for (int u = 0; u < 4; ++u)
            #pragma unroll
            for (int v = 0; v < 4; ++v) a3[u][v] = 0ull;
        for (int kc = 0; kc < 64; kc += 4) {
            ulonglong2 gA0 = *(const ulonglong2*)(gsb + (kc + 0) * PS4 + px0);
            ulonglong2 gB0 = *(const ulonglong2*)(gsb + (kc + 0) * PS4 + px0 + 64);
            ulonglong2 gA1 = *(const ulonglong2*)(gsb + (kc + 1) * PS4 + px0);
            ulonglong2 gB1 = *(const ulonglong2*)(gsb + (kc + 1) * PS4 + px0 + 64);
            ulonglong2 gA2 = *(const ulonglong2*)(gsb + (kc + 2) * PS4 + px0);
            ulonglong2 gB2 = *(const ulonglong2*)(gsb + (kc + 2) * PS4 + px0 + 64);
            ulonglong2 gA3 = *(const ulonglong2*)(gsb + (kc + 3) * PS4 + px0);
            ulonglong2 gB3 = *(const ulonglong2*)(gsb + (kc + 3) * PS4 + px0 + 64);
            #pragma unroll
            for (int u = 0; u < 4; ++u) {
                float4 wv = __ldg((const float4*)(wb5 + (oc0 + u) * Cc + kc));
                u64 w0 = splat2(wv.x), w1s = splat2(wv.y);
                u64 w2s = splat2(wv.z), w3s = splat2(wv.w);
                ffma2(a3[u][0], w0, gA0.x);  ffma2(a3[u][1], w0, gA0.y);
                ffma2(a3[u][2], w0, gB0.x);  ffma2(a3[u][3], w0, gB0.y);
                ffma2(a3[u][0], w1s, gA1.x); ffma2(a3[u][1], w1s, gA1.y);
                ffma2(a3[u][2], w1s, gB1.x); ffma2(a3[u][3], w1s, gB1.y);
                ffma2(a3[u][0], w2s, gA2.x); ffma2(a3[u][1], w2s, gA2.y);
                ffma2(a3[u][2], w2s, gB2.x); ffma2(a3[u][3], w2s, gB2.y);
                ffma2(a3[u][0], w3s, gA3.x); ffma2(a3[u][1], w3s, gA3.y);
                ffma2(a3[u][2], w3s, gB3.x); ffma2(a3[u][3], w3s, gB3.y);
            }
        }
        float* ob = out + b * Cc * HWp + pix0 + px0;
        #pragma unroll
        for (int u = 0; u < 4; ++u) {
            int o = oc0 + u;
            float gm = __ldg(&gamma[o]);
            float bias = __ldg(&b5[o]);
            float2 p0 = unpack2(a3[u][0]), p1 = unpack2(a3[u][1]);
            float2 p2 = unpack2(a3[u][2]), p3 = unpack2(a3[u][3]);
            float4 yv0 = *(const float4*)(ysb + o * PS4 + px0);
            float4 r0;
            r0.x = yv0.x + (p0.x + bias) * gm;
            r0.y = yv0.y + (p0.y + bias) * gm;
            r0.z = yv0.z + (p1.x + bias) * gm;
            r0.w = yv0.w + (p1.y + bias) * gm;
            *(float4*)(ob + o * HWp) = r0;
            float4 yv1 = *(const float4*)(ysb + o * PS4 + px0 + 64);
            float4 r1;
            r1.x = yv1.x + (p2.x + bias) * gm;
            r1.y = yv1.y + (p2.y + bias) * gm;
            r1.z = yv1.z + (p3.x + bias) * gm;
            r1.w = yv1.w + (p3.y + bias) * gm;
            *(float4*)(ob + o * HWp + 64) = r1;
        }
    }
}

// ---------------- launch ----------------
extern "C" void kernel_launch(void* const* d_in, const int* in_sizes, int n_in,
                              void* d_out, int out_size) {
    const float* inp   = (const float*)d_in[0];
    const float* probs = (const float*)d_in[1];
    const float* ln1w  = (const float*)d_in[2];
    const float* ln1b  = (const float*)d_in[3];
    const float* ln2w  = (const float*)d_in[4];
    const float* ln2b  = (const float*)d_in[5];
    const float* w1    = (const float*)d_in[6];
    const float* b1    = (const float*)d_in[7];
    const float* la1   = (const float*)d_in[8];
    const float* lb1   = (const float*)d_in[9];
    const float* w2    = (const float*)d_in[10];
    const float* b2    = (const float*)d_in[11];
    const float* la2   = (const float*)d_in[12];
    const float* lb2   = (const float*)d_in[13];
    const float* wsca  = (const float*)d_in[14];
    const float* bsca  = (const float*)d_in[15];
    const float* lasca = (const float*)d_in[16];
    const float* lbsca = (const float*)d_in[17];
    const float* w3    = (const float*)d_in[18];
    const float* b3    = (const float*)d_in[19];
    const float* la3   = (const float*)d_in[20];
    const float* lb3   = (const float*)d_in[21];
    const float* w4    = (const float*)d_in[22];
    const float* b4    = (const float*)d_in[23];
    const float* la4   = (const float*)d_in[24];
    const float* lb4   = (const float*)d_in[25];
    const float* w5    = (const float*)d_in[26];
    const float* b5    = (const float*)d_in[27];
    const float* la5   = (const float*)d_in[28];
    const float* lb5   = (const float*)d_in[29];
    const float* beta  = (const float*)d_in[30];
    const float* gamma = (const float*)d_in[31];
    float* out = (float*)d_out;

    const int SM4 = (3 * 64 * PS4) * (int)sizeof(float);   // 101,376
    cudaFuncSetAttribute(k4_kernel, cudaFuncAttributeMaxDynamicSharedMemorySize, SM4);

    k_weights<<<dim3(6, Bn), 256>>>(probs,
                                    w1, la1, lb1, w2, la2, lb2,
                                    wsca, lasca, lbsca, w3, la3, lb3,
                                    w4, la4, lb4, w5, la5, lb5);
    k1_kernel<<<dim3(HWp / 128, Bn), 256>>>(inp, ln1w, ln1b, b1);
    k2_kernel<<<dim3(Hh / 4, Cc, Bn), 256>>>(b2);
    k4_kernel<<<dim3(HWp / 128, Bn), 256, SM4>>>(inp, ln2w, ln2b, bsca, b3, b4, b5, beta, gamma, out);
}

// round 15
// speedup vs baseline: 1.0626x; 1.0626x over previous
#include <cuda_runtime.h>

// ---------------- problem constants ----------------
#define Bn   4
#define Cc   64
#define DWc  128
#define Hh   256
#define Ww   256
#define HWp  65536            // H*W
#define EPSv 1e-6f
#define SCAL 2.0f

typedef unsigned long long u64;

// ---------------- packed f32x2 helpers (sm_103a FFMA2 path) ----------------
__device__ __forceinline__ u64 splat2(float w) {
    u64 r; unsigned int wi = __float_as_uint(w);
    asm("mov.b64 %0, {%1, %1};" : "=l"(r) : "r"(wi));
    return r;
}
__device__ __forceinline__ void ffma2(u64& d, u64 a, u64 b) {
    asm("fma.rn.f32x2 %0, %1, %2, %0;" : "+l"(d) : "l"(a), "l"(b));
}
__device__ __forceinline__ u64 add2(u64 a, u64 b) {
    u64 r; asm("add.rn.f32x2 %0, %1, %2;" : "=l"(r) : "l"(a), "l"(b)); return r;
}
__device__ __forceinline__ u64 mul2(u64 a, u64 b) {
    u64 r; asm("mul.rn.f32x2 %0, %1, %2;" : "=l"(r) : "l"(a), "l"(b)); return r;
}
__device__ __forceinline__ float2 unpack2(u64 v) {
    unsigned lo, hi;
    asm("mov.b64 {%0, %1}, %2;" : "=r"(lo), "=r"(hi) : "l"(v));
    float2 f; f.x = __uint_as_float(lo); f.y = __uint_as_float(hi);
    return f;
}

// ---------------- device scratch (no cudaMalloc allowed) ----------------
__device__ float g_w1  [Bn * DWc * Cc];
__device__ float g_w2  [Bn * DWc * 9];
__device__ float g_wsca[Bn * Cc * Cc];
__device__ float g_w3  [Bn * Cc * Cc];
__device__ float g_w4  [Bn * DWc * Cc];
__device__ float g_w5  [Bn * Cc * Cc];
__device__ float g_t1  [Bn * DWc * HWp];    // conv1 out
__device__ float g_xg  [Bn * Cc  * HWp];    // after simple_gate
__device__ float g_part[Bn * Cc * 64];      // deterministic pool partials

// ---------------- K0: gate + effective weights ----------------
__device__ __forceinline__ void mix1x1(const float* w, const float* la, const float* lb,
                                       float* dst, int O, int e, float gs, int t) {
    const float* lae = la + e * 4 * 64;
    int N = O * 64;
    for (int idx = t; idx < N; idx += 256) {
        int o = idx >> 6, i = idx & 63;
        const float* lbo = lb + (e * O + o) * 4;
        dst[idx] = w[idx] + gs * (lbo[0] * lae[i] + lbo[1] * lae[64 + i] +
                                  lbo[2] * lae[128 + i] + lbo[3] * lae[192 + i]);
    }
}

__global__ void k_weights(const float* __restrict__ probs,
                          const float* w1, const float* la1, const float* lb1,
                          const float* w2, const float* la2, const float* lb2,
                          const float* wsca, const float* lasca, const float* lbsca,
                          const float* w3, const float* la3, const float* lb3,
                          const float* w4, const float* la4, const float* lb4,
                          const float* w5, const float* la5, const float* lb5) {
    int b = blockIdx.y, job = blockIdx.x, t = threadIdx.x;
    float p0 = probs[b * 3 + 0], p1 = probs[b * 3 + 1], p2 = probs[b * 3 + 2];
    int e = 0; float g = p0;
    if (p1 > g) { g = p1; e = 1; }
    if (p2 > g) { g = p2; e = 2; }
    float gs = g * SCAL;

    if (job == 0) {
        mix1x1(w1, la1, lb1, g_w1 + b * DWc * Cc, DWc, e, gs, t);
    } else if (job == 1) {
        for (int idx = t; idx < DWc * 9; idx += 256) {
            int row = idx / 3, col = idx - row * 3;
            const float* lbo = lb2 + (e * 384 + row) * 12;
            const float* lae = la2 + e * 36 + col;
            float acc = w2[idx];
            #pragma unroll
            for (int r = 0; r < 12; ++r) acc += gs * lbo[r] * lae[r * 3];
            g_w2[b * DWc * 9 + idx] = acc;
        }
    } else if (job == 2) {
        mix1x1(wsca, lasca, lbsca, g_wsca + b * Cc * Cc, Cc, e, gs, t);
    } else if (job == 3) {
        mix1x1(w3, la3, lb3, g_w3 + b * Cc * Cc, Cc, e, gs, t);
    } else if (job == 4) {
        mix1x1(w4, la4, lb4, g_w4 + b * DWc * Cc, DWc, e, gs, t);
    } else {
        mix1x1(w5, la5, lb5, g_w5 + b * Cc * Cc, Cc, e, gs, t);
    }
}

// ---------------- K1: LN1 + conv1 (1x1, 64->128) ----------------
// grid (512, B), block 256.  Tile = 128 px.  Thread: 8 oc x 8 px ({px0..+3, px0+64..+67}).
// Weights straight from gmem (L1-cached broadcast float4); x in smem stride 132.
#define XS1 132
__global__ void __launch_bounds__(256, 2)
k1_kernel(const float* __restrict__ inp,
          const float* __restrict__ ln1w, const float* __restrict__ ln1b,
          const float* __restrict__ b1) {
    __shared__ float xs[64 * XS1];
    __shared__ float sred[256], qred[256], smean[128], sinv[128];
    __shared__ float lnws[64], lnbs[64];

    int b = blockIdx.y;
    int pix0 = blockIdx.x * 128;
    int t = threadIdx.x;

    if (t < 64) { lnws[t] = ln1w[t]; lnbs[t] = ln1b[t]; }

    const float* ib = inp + b * Cc * HWp + pix0;
    #pragma unroll
    for (int it = 0; it < 32; ++it) {
        int idx = it * 256 + t;
        int c = idx >> 7, p = idx & 127;
        xs[c * XS1 + p] = ib[c * HWp + p];
    }
    __syncthreads();

    // LN1 (conflict-free): thread -> pixel p = t&127, half hh = t>>7 (32 channels)
    {
        int p = t & 127, hh = t >> 7;
        float s = 0.f, qs = 0.f;
        #pragma unroll
        for (int c = 0; c < 32; ++c) {
            float v = xs[(hh * 32 + c) * XS1 + p];
            s += v; qs += v * v;
        }
        sred[t] = s; qred[t] = qs;
        __syncthreads();
        if (t < 128) {
            float S = sred[t] + sred[t + 128];
            float Q = qred[t] + qred[t + 128];
            float mean = S * (1.f / 64.f);
            float var  = Q * (1.f / 64.f) - mean * mean;
            smean[t] = mean;
            sinv[t]  = rsqrtf(var + EPSv);
        }
        __syncthreads();
        float mean = smean[p], inv = sinv[p];
        #pragma unroll
        for (int c = 0; c < 32; ++c) {
            int ch = hh * 32 + c;
            float v = xs[ch * XS1 + p];
            xs[ch * XS1 + p] = (v - mean) * inv * lnws[ch] + lnbs[ch];
        }
    }
    __syncthreads();

    // GEMM: 128 oc x 128 px, K=64.  Thread: 8 oc x 8 px.  Weights via __ldg float4.
    int oc0 = (t >> 4) * 8, px0 = (t & 15) * 4;
    const float* wb = g_w1 + b * DWc * Cc;
    u64 acc[8][4];
    #pragma unroll
    for (int u = 0; u < 8; ++u)
        #pragma unroll
        for (int v = 0; v < 4; ++v) acc[u][v] = 0ull;

    for (int kc = 0; kc < 64; kc += 4) {
        ulonglong2 xA0 = *(const ulonglong2*)(xs + (kc + 0) * XS1 + px0);
        ulonglong2 xB0 = *(const ulonglong2*)(xs + (kc + 0) * XS1 + px0 + 64);
        ulonglong2 xA1 = *(const ulonglong2*)(xs + (kc + 1) * XS1 + px0);
        ulonglong2 xB1 = *(const ulonglong2*)(xs + (kc + 1) * XS1 + px0 + 64);
        ulonglong2 xA2 = *(const ulonglong2*)(xs + (kc + 2) * XS1 + px0);
        ulonglong2 xB2 = *(const ulonglong2*)(xs + (kc + 2) * XS1 + px0 + 64);
        ulonglong2 xA3 = *(const ulonglong2*)(xs + (kc + 3) * XS1 + px0);
        ulonglong2 xB3 = *(const ulonglong2*)(xs + (kc + 3) * XS1 + px0 + 64);
        #pragma unroll
        for (int u = 0; u < 8; ++u) {
            float4 wv = __ldg((const float4*)(wb + (oc0 + u) * Cc + kc));
            u64 w0 = splat2(wv.x), w1s = splat2(wv.y);
            u64 w2s = splat2(wv.z), w3s = splat2(wv.w);
            ffma2(acc[u][0], w0, xA0.x);  ffma2(acc[u][1], w0, xA0.y);
            ffma2(acc[u][2], w0, xB0.x);  ffma2(acc[u][3], w0, xB0.y);
            ffma2(acc[u][0], w1s, xA1.x); ffma2(acc[u][1], w1s, xA1.y);
            ffma2(acc[u][2], w1s, xB1.x); ffma2(acc[u][3], w1s, xB1.y);
            ffma2(acc[u][0], w2s, xA2.x); ffma2(acc[u][1], w2s, xA2.y);
            ffma2(acc[u][2], w2s, xB2.x); ffma2(acc[u][3], w2s, xB2.y);
            ffma2(acc[u][0], w3s, xA3.x); ffma2(acc[u][1], w3s, xA3.y);
            ffma2(acc[u][2], w3s, xB3.x); ffma2(acc[u][3], w3s, xB3.y);
        }
    }

    float* ob = g_t1 + b * DWc * HWp + pix0 + px0;
    #pragma unroll
    for (int u = 0; u < 8; ++u) {
        float bias = __ldg(&b1[oc0 + u]);
        float2 p0 = unpack2(acc[u][0]), p1 = unpack2(acc[u][1]);
        float2 p2 = unpack2(acc[u][2]), p3 = unpack2(acc[u][3]);
        float4 r0 = make_float4(p0.x + bias, p0.y + bias, p1.x + bias, p1.y + bias);
        float4 r1 = make_float4(p2.x + bias, p2.y + bias, p3.x + bias, p3.y + bias);
        *(float4*)(ob + (oc0 + u) * HWp)      = r0;
        *(float4*)(ob + (oc0 + u) * HWp + 64) = r1;
    }
}

// ---------------- K2: depthwise 3x3 + simple_gate + pool partials ----------------
// Padded smem (258 cols, zeroed borders) -> no column predicates in the 9-tap loop.
__global__ void k2_kernel(const float* __restrict__ b2) {
    __shared__ float s0[6][258];
    __shared__ float s1[6][258];
    __shared__ float red[8];

    int b = blockIdx.z, c = blockIdx.y;
    int r0 = blockIdx.x * 4;
    int t = threadIdx.x;

    const float* t1a = g_t1 + (b * DWc + c) * HWp;
    const float* t1b = g_t1 + (b * DWc + c + 64) * HWp;

    // zero left/right borders (12 slots per array)
    if (t < 12) {
        int lr = t >> 1, col = (t & 1) ? 257 : 0;
        s0[lr][col] = 0.f;
        s1[lr][col] = 0.f;
    }
    #pragma unroll
    for (int lr = 0; lr < 6; ++lr) {
        int gr = r0 + lr - 1;
        bool ok = (gr >= 0 && gr < Hh);
        s0[lr][t + 1] = ok ? t1a[gr * Ww + t] : 0.f;
        s1[lr][t + 1] = ok ? t1b[gr * Ww + t] : 0.f;
    }
    __syncthreads();

    float wa[9], wb9[9];
    const float* w2a = g_w2 + (b * DWc + c) * 9;
    const float* w2b = g_w2 + (b * DWc + c + 64) * 9;
    #pragma unroll
    for (int i = 0; i < 9; ++i) { wa[i] = __ldg(&w2a[i]); wb9[i] = __ldg(&w2b[i]); }
    float biasA = __ldg(&b2[c]), biasB = __ldg(&b2[c + 64]);

    float* xgp = g_xg + (b * Cc + c) * HWp;
    float lsum = 0.f;
    int w = t;
    #pragma unroll
    for (int j = 0; j < 4; ++j) {
        float a0 = biasA, a1 = biasB;
        #pragma unroll
        for (int kh = 0; kh < 3; ++kh) {
            #pragma unroll
            for (int kw = 0; kw < 3; ++kw) {
                a0 += wa[kh * 3 + kw] * s0[j + kh][w + kw];
                a1 += wb9[kh * 3 + kw] * s1[j + kh][w + kw];
            }
        }
        float val = a0 * a1;
        xgp[(r0 + j) * Ww + w] = val;
        lsum += val;
    }

    // warp shuffle reduction + one cross-warp step (deterministic)
    #pragma unroll
    for (int o = 16; o > 0; o >>= 1)
        lsum += __shfl_xor_sync(0xffffffffu, lsum, o);
    if ((t & 31) == 0) red[t >> 5] = lsum;
    __syncthreads();
    if (t == 0) {
        float s = red[0] + red[1] + red[2] + red[3]
                + red[4] + red[5] + red[6] + red[7];
        g_part[(b * Cc + c) * 64 + blockIdx.x] = s;
    }
}

// ---------------- K4: fused per-pixel tail ----------------
// grid (512, B), block 256.  Tile = 128 px, thread = 8 px ({px0..+3, px0+64..+67}).
// TWO pixel buffers only: xsb holds x -> LN2-out -> (after full barrier) gate-out.
#define PS4 132
__global__ void __launch_bounds__(256, 2)
k4_kernel(const float* __restrict__ inp,
          const float* __restrict__ ln2w, const float* __restrict__ ln2b,
          const float* __restrict__ bsca,
          const float* __restrict__ b3, const float* __restrict__ b4,
          const float* __restrict__ b5,
          const float* __restrict__ beta, const float* __restrict__ gamma,
          float* __restrict__ out) {
    extern __shared__ float sm[];
    float* xsb = sm;                   // 64*132 (x -> LN2 out -> gate out)
    float* ysb = xsb + 64 * PS4;       // 64*132 (residual y)
    __shared__ float sred[256], qred[256], smean[128], sinv[128];
    __shared__ float lnws[64], lnbs[64];
    __shared__ float s_pool[64], s_sca[64];

    int b = blockIdx.y;
    int pix0 = blockIdx.x * 128;
    int t = threadIdx.x;

    if (t < 64) { lnws[t] = ln2w[t]; lnbs[t] = ln2b[t]; }
    // pool mean from partials (k3 fold)
    if (t < 64) {
        float s = 0.f;
        const float4* pp = (const float4*)(g_part + (b * Cc + t) * 64);
        #pragma unroll
        for (int k = 0; k < 16; ++k) {
            float4 v = pp[k];
            s += (v.x + v.y) + (v.z + v.w);
        }
        s_pool[t] = s * (1.f / (float)HWp);
    }
    __syncthreads();
    if (t < 64) {
        const float* wr = g_wsca + b * Cc * Cc + t * Cc;
        float acc = __ldg(&bsca[t]);
        #pragma unroll
        for (int i = 0; i < 64; ++i) acc += wr[i] * s_pool[i];
        s_sca[t] = acc;
    }
    __syncthreads();

    const float* xgb = g_xg + b * Cc * HWp + pix0;
    const float* ib  = inp  + b * Cc * HWp + pix0;
    #pragma unroll
    for (int it = 0; it < 32; ++it) {
        int idx = it * 256 + t;
        int c = idx >> 7, p = idx & 127;
        float sc = s_sca[c];
        xsb[c * PS4 + p] = xgb[c * HWp + p] * sc;
        ysb[c * PS4 + p] = ib[c * HWp + p];
    }
    __syncthreads();

    int tg = t >> 4, px0 = (t & 15) * 4;
    const float* wb3 = g_w3 + b * Cc * Cc;
    const float* wb4 = g_w4 + b * DWc * Cc;
    const float* wb5 = g_w5 + b * Cc * Cc;

    // matvec1: conv3 (64x64); thread 4 oc x 8 px.  y = inp + (t3+bias)*beta
    {
        int oc0 = tg * 4;
        u64 a1[4][4];
        #pragma unroll
        for (int u = 0; u < 4; ++u)
            #pragma unroll
            for (int v = 0; v < 4; ++v) a1[u][v] = 0ull;
        for (int kc = 0; kc < 64; kc += 4) {
            ulonglong2 xA0 = *(const ulonglong2*)(xsb + (kc + 0) * PS4 + px0);
            ulonglong2 xB0 = *(const ulonglong2*)(xsb + (kc + 0) * PS4 + px0 + 64);
            ulonglong2 xA1 = *(const ulonglong2*)(xsb + (kc + 1) * PS4 + px0);
            ulonglong2 xB1 = *(const ulonglong2*)(xsb + (kc + 1) * PS4 + px0 + 64);
            ulonglong2 xA2 = *(const ulonglong2*)(xsb + (kc + 2) * PS4 + px0);
            ulonglong2 xB2 = *(const ulonglong2*)(xsb + (kc + 2) * PS4 + px0 + 64);
            ulonglong2 xA3 = *(const ulonglong2*)(xsb + (kc + 3) * PS4 + px0);
            ulonglong2 xB3 = *(const ulonglong2*)(xsb + (kc + 3) * PS4 + px0 + 64);
            #pragma unroll
            for (int u = 0; u < 4; ++u) {
                float4 wv = __ldg((const float4*)(wb3 + (oc0 + u) * Cc + kc));
                u64 w0 = splat2(wv.x), w1s = splat2(wv.y);
                u64 w2s = splat2(wv.z), w3s = splat2(wv.w);
                ffma2(a1[u][0], w0, xA0.x);  ffma2(a1[u][1], w0, xA0.y);
                ffma2(a1[u][2], w0, xB0.x);  ffma2(a1[u][3], w0, xB0.y);
                ffma2(a1[u][0], w1s, xA1.x); ffma2(a1[u][1], w1s, xA1.y);
                ffma2(a1[u][2], w1s, xB1.x); ffma2(a1[u][3], w1s, xB1.y);
                ffma2(a1[u][0], w2s, xA2.x); ffma2(a1[u][1], w2s, xA2.y);
                ffma2(a1[u][2], w2s, xB2.x); ffma2(a1[u][3], w2s, xB2.y);
                ffma2(a1[u][0], w3s, xA3.x); ffma2(a1[u][1], w3s, xA3.y);
                ffma2(a1[u][2], w3s, xB3.x); ffma2(a1[u][3], w3s, xB3.y);
            }
        }
        #pragma unroll
        for (int u = 0; u < 4; ++u) {
            int o = oc0 + u;
            float bt = __ldg(&beta[o]);
            float bias = __ldg(&b3[o]);
            float2 p0 = unpack2(a1[u][0]), p1 = unpack2(a1[u][1]);
            float2 p2 = unpack2(a1[u][2]), p3 = unpack2(a1[u][3]);
            float4* yv0 = (float4*)(ysb + o * PS4 + px0);
            float4 y0 = *yv0;
            y0.x += (p0.x + bias) * bt;
            y0.y += (p0.y + bias) * bt;
            y0.z += (p1.x + bias) * bt;
            y0.w += (p1.y + bias) * bt;
            *yv0 = y0;
            float4* yv1 = (float4*)(ysb + o * PS4 + px0 + 64);
            float4 y1 = *yv1;
            y1.x += (p2.x + bias) * bt;
            y1.y += (p2.y + bias) * bt;
            y1.z += (p3.x + bias) * bt;
            y1.w += (p3.y + bias) * bt;
            *yv1 = y1;
        }
    }
    __syncthreads();

    // LN2 (conflict-free): thread -> pixel p = t&127, half hh = t>>7 (32 channels).
    // Output -> xsb (dead after matvec1).
    {
        int p = t & 127, hh = t >> 7;
        float s = 0.f, qs = 0.f;
        #pragma unroll
        for (int c = 0; c < 32; ++c) {
            float v = ysb[(hh * 32 + c) * PS4 + p];
            s += v; qs += v * v;
        }
        sred[t] = s; qred[t] = qs;
        __syncthreads();
        if (t < 128) {
            float S = sred[t] + sred[t + 128];
            float Q = qred[t] + qred[t + 128];
            float mean = S * (1.f / 64.f);
            float var  = Q * (1.f / 64.f) - mean * mean;
            smean[t] = mean;
            sinv[t]  = rsqrtf(var + EPSv);
        }
        __syncthreads();
        float mean = smean[p], inv = sinv[p];
        #pragma unroll
        for (int c = 0; c < 32; ++c) {
            int ch = hh * 32 + c;
            float v = ysb[ch * PS4 + p];
            xsb[ch * PS4 + p] = (v - mean) * inv * lnws[ch] + lnbs[ch];
        }
    }
    __syncthreads();

    // matvec2: conv4 (128x64) + simple_gate. oc = tg + 16*j keeps gate pairs in-thread.
    // Full accumulator held in registers -> after a barrier, gate output overwrites xsb.
    {
        u64 a2[8][4];
        #pragma unroll
        for (int j = 0; j < 8; ++j)
            #pragma unroll
            for (int v = 0; v < 4; ++v) a2[j][v] = 0ull;
        for (int kc = 0; kc < 64; kc += 4) {
            ulonglong2 zA0 = *(const ulonglong2*)(xsb + (kc + 0) * PS4 + px0);
            ulonglong2 zB0 = *(const ulonglong2*)(xsb + (kc + 0) * PS4 + px0 + 64);
            ulonglong2 zA1 = *(const ulonglong2*)(xsb + (kc + 1) * PS4 + px0);
            ulonglong2 zB1 = *(const ulonglong2*)(xsb + (kc + 1) * PS4 + px0 + 64);
            ulonglong2 zA2 = *(const ulonglong2*)(xsb + (kc + 2) * PS4 + px0);
            ulonglong2 zB2 = *(const ulonglong2*)(xsb + (kc + 2) * PS4 + px0 + 64);
            ulonglong2 zA3 = *(const ulonglong2*)(xsb + (kc + 3) * PS4 + px0);
            ulonglong2 zB3 = *(const ulonglong2*)(xsb + (kc + 3) * PS4 + px0 + 64);
            #pragma unroll
            for (int j = 0; j < 8; ++j) {
                float4 wv = __ldg((const float4*)(wb4 + (tg + 16 * j) * Cc + kc));
                u64 w0 = splat2(wv.x), w1s = splat2(wv.y);
                u64 w2s = splat2(wv.z), w3s = splat2(wv.w);
                ffma2(a2[j][0], w0, zA0.x);  ffma2(a2[j][1], w0, zA0.y);
                ffma2(a2[j][2], w0, zB0.x);  ffma2(a2[j][3], w0, zB0.y);
                ffma2(a2[j][0], w1s, zA1.x); ffma2(a2[j][1], w1s, zA1.y);
                ffma2(a2[j][2], w1s, zB1.x); ffma2(a2[j][3], w1s, zB1.y);
                ffma2(a2[j][0], w2s, zA2.x); ffma2(a2[j][1], w2s, zA2.y);
                ffma2(a2[j][2], w2s, zB2.x); ffma2(a2[j][3], w2s, zB2.y);
                ffma2(a2[j][0], w3s, zA3.x); ffma2(a2[j][1], w3s, zA3.y);
                ffma2(a2[j][2], w3s, zB3.x); ffma2(a2[j][3], w3s, zB3.y);
            }
        }
        __syncthreads();   // all reads of xsb (LN2 out) complete before overwrite
        #pragma unroll
        for (int j = 0; j < 4; ++j) {
            int o = tg + 16 * j;
            u64 bl = splat2(__ldg(&b4[o]));
            u64 bh = splat2(__ldg(&b4[o + 64]));
            ulonglong2 gv0, gv1;
            gv0.x = mul2(add2(a2[j][0], bl), add2(a2[j + 4][0], bh));
            gv0.y = mul2(add2(a2[j][1], bl), add2(a2[j + 4][1], bh));
            gv1.x = mul2(add2(a2[j][2], bl), add2(a2[j + 4][2], bh));
            gv1.y = mul2(add2(a2[j][3], bl), add2(a2[j + 4][3], bh));
            *(ulonglong2*)(xsb + o * PS4 + px0)      = gv0;
            *(ulonglong2*)(xsb + o * PS4 + px0 + 64) = gv1;
        }
    }
    __syncthreads();

    // matvec3: conv5 (64x64);  out = y + (t5+bias)*gamma   (gate input now in xsb)
    {
        int oc0 = tg * 4;
        u64 a3[4][4];
        #pragma unroll
        for (int u = 0; u < 4; ++u)
            #pragma unroll
            for (int v = 0; v < 4; ++v) a3[u][v] = 0ull;
        for (int kc = 0; kc < 64; kc += 4) {
            ulonglong2 gA0 = *(const ulonglong2*)(xsb + (kc + 0) * PS4 + px0);
            ulonglong2 gB0 = *(const ulonglong2*)(xsb + (kc + 0) * PS4 + px0 + 64);
            ulonglong2 gA1 = *(const ulonglong2*)(xsb + (kc + 1) * PS4 + px0);
            ulonglong2 gB1 = *(const ulonglong2*)(xsb + (kc + 1) * PS4 + px0 + 64);
            ulonglong2 gA2 = *(const ulonglong2*)(xsb + (kc + 2) * PS4 + px0);
            ulonglong2 gB2 = *(const ulonglong2*)(xsb + (kc + 2) * PS4 + px0 + 64);
            ulonglong2 gA3 = *(const ulonglong2*)(xsb + (kc + 3) * PS4 + px0);
            ulonglong2 gB3 = *(const ulonglong2*)(xsb + (kc + 3) * PS4 + px0 + 64);
            #pragma unroll
            for (int u = 0; u < 4; ++u) {
                float4 wv = __ldg((const float4*)(wb5 + (oc0 + u) * Cc + kc));
                u64 w0 = splat2(wv.x), w1s = splat2(wv.y);
                u64 w2s = splat2(wv.z), w3s = splat2(wv.w);
                ffma2(a3[u][0], w0, gA0.x);  ffma2(a3[u][1], w0, gA0.y);
                ffma2(a3[u][2], w0, gB0.x);  ffma2(a3[u][3], w0, gB0.y);
                ffma2(a3[u][0], w1s, gA1.x); ffma2(a3[u][1], w1s, gA1.y);
                ffma2(a3[u][2], w1s, gB1.x); ffma2(a3[u][3], w1s, gB1.y);
                ffma2(a3[u][0], w2s, gA2.x); ffma2(a3[u][1], w2s, gA2.y);
                ffma2(a3[u][2], w2s, gB2.x); ffma2(a3[u][3], w2s, gB2.y);
                ffma2(a3[u][0], w3s, gA3.x); ffma2(a3[u][1], w3s, gA3.y);
                ffma2(a3[u][2], w3s, gB3.x); ffma2(a3[u][3], w3s, gB3.y);
            }
        }
        float* ob = out + b * Cc * HWp + pix0 + px0;
        #pragma unroll
        for (int u = 0; u < 4; ++u) {
            int o = oc0 + u;
            float gm = __ldg(&gamma[o]);
            float bias = __ldg(&b5[o]);
            float2 p0 = unpack2(a3[u][0]), p1 = unpack2(a3[u][1]);
            float2 p2 = unpack2(a3[u][2]), p3 = unpack2(a3[u][3]);
            float4 yv0 = *(const float4*)(ysb + o * PS4 + px0);
            float4 r0;
            r0.x = yv0.x + (p0.x + bias) * gm;
            r0.y = yv0.y + (p0.y + bias) * gm;
            r0.z = yv0.z + (p1.x + bias) * gm;
            r0.w = yv0.w + (p1.y + bias) * gm;
            *(float4*)(ob + o * HWp) = r0;
            float4 yv1 = *(const float4*)(ysb + o * PS4 + px0 + 64);
            float4 r1;
            r1.x = yv1.x + (p2.x + bias) * gm;
            r1.y = yv1.y + (p2.y + bias) * gm;
            r1.z = yv1.z + (p3.x + bias) * gm;
            r1.w = yv1.w + (p3.y + bias) * gm;
            *(float4*)(ob + o * HWp + 64) = r1;
        }
    }
}

// ---------------- launch ----------------
extern "C" void kernel_launch(void* const* d_in, const int* in_sizes, int n_in,
                              void* d_out, int out_size) {
    const float* inp   = (const float*)d_in[0];
    const float* probs = (const float*)d_in[1];
    const float* ln1w  = (const float*)d_in[2];
    const float* ln1b  = (const float*)d_in[3];
    const float* ln2w  = (const float*)d_in[4];
    const float* ln2b  = (const float*)d_in[5];
    const float* w1    = (const float*)d_in[6];
    const float* b1    = (const float*)d_in[7];
    const float* la1   = (const float*)d_in[8];
    const float* lb1   = (const float*)d_in[9];
    const float* w2    = (const float*)d_in[10];
    const float* b2    = (const float*)d_in[11];
    const float* la2   = (const float*)d_in[12];
    const float* lb2   = (const float*)d_in[13];
    const float* wsca  = (const float*)d_in[14];
    const float* bsca  = (const float*)d_in[15];
    const float* lasca = (const float*)d_in[16];
    const float* lbsca = (const float*)d_in[17];
    const float* w3    = (const float*)d_in[18];
    const float* b3    = (const float*)d_in[19];
    const float* la3   = (const float*)d_in[20];
    const float* lb3   = (const float*)d_in[21];
    const float* w4    = (const float*)d_in[22];
    const float* b4    = (const float*)d_in[23];
    const float* la4   = (const float*)d_in[24];
    const float* lb4   = (const float*)d_in[25];
    const float* w5    = (const float*)d_in[26];
    const float* b5    = (const float*)d_in[27];
    const float* la5   = (const float*)d_in[28];
    const float* lb5   = (const float*)d_in[29];
    const float* beta  = (const float*)d_in[30];
    const float* gamma = (const float*)d_in[31];
    float* out = (float*)d_out;

    const int SM4 = (2 * 64 * PS4) * (int)sizeof(float);   // 67,584
    cudaFuncSetAttribute(k4_kernel, cudaFuncAttributeMaxDynamicSharedMemorySize, SM4);

    k_weights<<<dim3(6, Bn), 256>>>(probs,
                                    w1, la1, lb1, w2, la2, lb2,
                                    wsca, lasca, lbsca, w3, la3, lb3,
                                    w4, la4, lb4, w5, la5, lb5);
    k1_kernel<<<dim3(HWp / 128, Bn), 256>>>(inp, ln1w, ln1b, b1);
    k2_kernel<<<dim3(Hh / 4, Cc, Bn), 256>>>(b2);
    k4_kernel<<<dim3(HWp / 128, Bn), 256, SM4>>>(inp, ln2w, ln2b, bsca, b3, b4, b5, beta, gamma, out);
}

// round 17
// speedup vs baseline: 1.3162x; 1.2386x over previous
#include <cuda_runtime.h>
#include <cuda_bf16.h>
#include <cstdint>

// ---------------- problem constants ----------------
#define Bn   4
#define Cc   64
#define DWc  128
#define Hh   256
#define Ww   256
#define HWp  65536            // H*W
#define EPSv 1e-6f
#define SCAL 2.0f

typedef unsigned long long u64;

// ---------------- packed f32x2 helpers (k1 scalar GEMM) ----------------
__device__ __forceinline__ u64 splat2(float w) {
    u64 r; unsigned int wi = __float_as_uint(w);
    asm("mov.b64 %0, {%1, %1};" : "=l"(r) : "r"(wi));
    return r;
}
__device__ __forceinline__ void ffma2(u64& d, u64 a, u64 b) {
    asm("fma.rn.f32x2 %0, %1, %2, %0;" : "+l"(d) : "l"(a), "l"(b));
}
__device__ __forceinline__ float2 unpack2(u64 v) {
    unsigned lo, hi;
    asm("mov.b64 {%0, %1}, %2;" : "=r"(lo), "=r"(hi) : "l"(v));
    float2 f; f.x = __uint_as_float(lo); f.y = __uint_as_float(hi);
    return f;
}

// ---------------- bf16 split helpers ----------------
__device__ __forceinline__ void split2(float v0, float v1, uint32_t& hp, uint32_t& lp) {
    __nv_bfloat16 h0 = __float2bfloat16(v0);
    __nv_bfloat16 h1 = __float2bfloat16(v1);
    __nv_bfloat16 l0 = __float2bfloat16(v0 - __bfloat162float(h0));
    __nv_bfloat16 l1 = __float2bfloat16(v1 - __bfloat162float(h1));
    hp = (uint32_t)__bfloat16_as_ushort(h0) | ((uint32_t)__bfloat16_as_ushort(h1) << 16);
    lp = (uint32_t)__bfloat16_as_ushort(l0) | ((uint32_t)__bfloat16_as_ushort(l1) << 16);
}

// mma.sync m16n8k16 bf16: D += A*B (fp32 accum) — baseline PTX, runs on sm_103 HMMA
__device__ __forceinline__ void mma_bf16(float* d, uint32_t a0, uint32_t a1,
                                         uint32_t a2, uint32_t a3,
                                         uint32_t b0, uint32_t b1) {
    asm volatile(
        "mma.sync.aligned.m16n8k16.row.col.f32.bf16.bf16.f32 "
        "{%0,%1,%2,%3}, {%4,%5,%6,%7}, {%8,%9}, {%0,%1,%2,%3};"
        : "+f"(d[0]), "+f"(d[1]), "+f"(d[2]), "+f"(d[3])
        : "r"(a0), "r"(a1), "r"(a2), "r"(a3), "r"(b0), "r"(b1));
}

// ---------------- device scratch (no cudaMalloc allowed) ----------------
__device__ float g_w1  [Bn * DWc * Cc];
__device__ float g_w2  [Bn * DWc * 9];
__device__ float g_wsca[Bn * Cc * Cc];
__device__ float g_t1  [Bn * DWc * HWp];
__device__ float g_xg  [Bn * Cc  * HWp];
__device__ float g_part[Bn * Cc * 64];
// mma B-fragment arrays: per (tile_n, kstep, lane) a uint4 {b0h,b1h,b0l,b1l}
__device__ uint4 g_f3[Bn * 8  * 4 * 32];   // w3: 64x64  -> 8 n-tiles
__device__ uint4 g_f4[Bn * 16 * 4 * 32];   // w4: 128x64 -> 16 n-tiles
__device__ uint4 g_f5[Bn * 8  * 4 * 32];   // w5: 64x64

// ---------------- K0: gate + effective weights (+ mma fragments) ----------------
__device__ __forceinline__ void mix1x1(const float* w, const float* la, const float* lb,
                                       float* dst, int O, int e, float gs, int t) {
    const float* lae = la + e * 4 * 64;
    int N = O * 64;
    for (int idx = t; idx < N; idx += 256) {
        int o = idx >> 6, i = idx & 63;
        const float* lbo = lb + (e * O + o) * 4;
        dst[idx] = w[idx] + gs * (lbo[0] * lae[i] + lbo[1] * lae[64 + i] +
                                  lbo[2] * lae[128 + i] + lbo[3] * lae[192 + i]);
    }
}
__device__ __forceinline__ float weff(const float* w, const float* lae, const float* lb,
                                      int O, int e, float gs, int n, int k) {
    const float* lbo = lb + (e * O + n) * 4;
    return w[n * 64 + k] + gs * (lbo[0] * lae[k] + lbo[1] * lae[64 + k] +
                                 lbo[2] * lae[128 + k] + lbo[3] * lae[192 + k]);
}
__device__ __forceinline__ void mix_frag(const float* w, const float* la, const float* lb,
                                         uint4* frag, int O, int e, float gs, int t) {
    const float* lae = la + e * 4 * 64;
    int entries = (O / 8) * 4 * 32;
    for (int idx = t; idx < entries; idx += 256) {
        int lane = idx & 31, ks = (idx >> 5) & 3, tile = idx >> 7;
        int g = lane >> 2, tt = lane & 3;
        int n = tile * 8 + g;
        int k0 = ks * 16 + 2 * tt;
        float v00 = weff(w, lae, lb, O, e, gs, n, k0);
        float v01 = weff(w, lae, lb, O, e, gs, n, k0 + 1);
        float v10 = weff(w, lae, lb, O, e, gs, n, k0 + 8);
        float v11 = weff(w, lae, lb, O, e, gs, n, k0 + 9);
        uint4 o;
        split2(v00, v01, o.x, o.z);
        split2(v10, v11, o.y, o.w);
        frag[(tile * 4 + ks) * 32 + lane] = o;
    }
}

__global__ void k_weights(const float* __restrict__ probs,
                          const float* w1, const float* la1, const float* lb1,
                          const float* w2, const float* la2, const float* lb2,
                          const float* wsca, const float* lasca, const float* lbsca,
                          const float* w3, const float* la3, const float* lb3,
                          const float* w4, const float* la4, const float* lb4,
                          const float* w5, const float* la5, const float* lb5) {
    int b = blockIdx.y, job = blockIdx.x, t = threadIdx.x;
    float p0 = probs[b * 3 + 0], p1 = probs[b * 3 + 1], p2 = probs[b * 3 + 2];
    int e = 0; float g = p0;
    if (p1 > g) { g = p1; e = 1; }
    if (p2 > g) { g = p2; e = 2; }
    float gs = g * SCAL;

    if (job == 0) {
        mix1x1(w1, la1, lb1, g_w1 + b * DWc * Cc, DWc, e, gs, t);
    } else if (job == 1) {
        for (int idx = t; idx < DWc * 9; idx += 256) {
            int row = idx / 3, col = idx - row * 3;
            const float* lbo = lb2 + (e * 384 + row) * 12;
            const float* lae = la2 + e * 36 + col;
            float acc = w2[idx];
            #pragma unroll
            for (int r = 0; r < 12; ++r) acc += gs * lbo[r] * lae[r * 3];
            g_w2[b * DWc * 9 + idx] = acc;
        }
    } else if (job == 2) {
        mix1x1(wsca, lasca, lbsca, g_wsca + b * Cc * Cc, Cc, e, gs, t);
    } else if (job == 3) {
        mix_frag(w3, la3, lb3, g_f3 + b * 1024, Cc, e, gs, t);
    } else if (job == 4) {
        mix_frag(w4, la4, lb4, g_f4 + b * 2048, DWc, e, gs, t);
    } else {
        mix_frag(w5, la5, lb5, g_f5 + b * 1024, Cc, e, gs, t);
    }
}

// ---------------- K1: LN1 + conv1 (1x1, 64->128), scalar FFMA2 (R15 state) ----------------
#define XS1 132
__global__ void __launch_bounds__(256, 2)
k1_kernel(const float* __restrict__ inp,
          const float* __restrict__ ln1w, const float* __restrict__ ln1b,
          const float* __restrict__ b1) {
    __shared__ float xs[64 * XS1];
    __shared__ float sred[256], qred[256], smean[128], sinv[128];
    __shared__ float lnws[64], lnbs[64];

    int b = blockIdx.y;
    int pix0 = blockIdx.x * 128;
    int t = threadIdx.x;

    if (t < 64) { lnws[t] = ln1w[t]; lnbs[t] = ln1b[t]; }

    const float* ib = inp + b * Cc * HWp + pix0;
    #pragma unroll
    for (int it = 0; it < 32; ++it) {
        int idx = it * 256 + t;
        int c = idx >> 7, p = idx & 127;
        xs[c * XS1 + p] = ib[c * HWp + p];
    }
    __syncthreads();

    {
        int p = t & 127, hh = t >> 7;
        float s = 0.f, qs = 0.f;
        #pragma unroll
        for (int c = 0; c < 32; ++c) {
            float v = xs[(hh * 32 + c) * XS1 + p];
            s += v; qs += v * v;
        }
        sred[t] = s; qred[t] = qs;
        __syncthreads();
        if (t < 128) {
            float S = sred[t] + sred[t + 128];
            float Q = qred[t] + qred[t + 128];
            float mean = S * (1.f / 64.f);
            float var  = Q * (1.f / 64.f) - mean * mean;
            smean[t] = mean;
            sinv[t]  = rsqrtf(var + EPSv);
        }
        __syncthreads();
        float mean = smean[p], inv = sinv[p];
        #pragma unroll
        for (int c = 0; c < 32; ++c) {
            int ch = hh * 32 + c;
            float v = xs[ch * XS1 + p];
            xs[ch * XS1 + p] = (v - mean) * inv * lnws[ch] + lnbs[ch];
        }
    }
    __syncthreads();

    int oc0 = (t >> 4) * 8, px0 = (t & 15) * 4;
    const float* wb = g_w1 + b * DWc * Cc;
    u64 acc[8][4];
    #pragma unroll
    for (int u = 0; u < 8; ++u)
        #pragma unroll
        for (int v = 0; v < 4; ++v) acc[u][v] = 0ull;

    for (int kc = 0; kc < 64; kc += 4) {
        ulonglong2 xA0 = *(const ulonglong2*)(xs + (kc + 0) * XS1 + px0);
        ulonglong2 xB0 = *(const ulonglong2*)(xs + (kc + 0) * XS1 + px0 + 64);
        ulonglong2 xA1 = *(const ulonglong2*)(xs + (kc + 1) * XS1 + px0);
        ulonglong2 xB1 = *(const ulonglong2*)(xs + (kc + 1) * XS1 + px0 + 64);
        ulonglong2 xA2 = *(const ulonglong2*)(xs + (kc + 2) * XS1 + px0);
        ulonglong2 xB2 = *(const ulonglong2*)(xs + (kc + 2) * XS1 + px0 + 64);
        ulonglong2 xA3 = *(const ulonglong2*)(xs + (kc + 3) * XS1 + px0);
        ulonglong2 xB3 = *(const ulonglong2*)(xs + (kc + 3) * XS1 + px0 + 64);
        #pragma unroll
        for (int u = 0; u < 8; ++u) {
            float4 wv = __ldg((const float4*)(wb + (oc0 + u) * Cc + kc));
            u64 w0 = splat2(wv.x), w1s = splat2(wv.y);
            u64 w2s = splat2(wv.z), w3s = splat2(wv.w);
            ffma2(acc[u][0], w0, xA0.x);  ffma2(acc[u][1], w0, xA0.y);
            ffma2(acc[u][2], w0, xB0.x);  ffma2(acc[u][3], w0, xB0.y);
            ffma2(acc[u][0], w1s, xA1.x); ffma2(acc[u][1], w1s, xA1.y);
            ffma2(acc[u][2], w1s, xB1.x); ffma2(acc[u][3], w1s, xB1.y);
            ffma2(acc[u][0], w2s, xA2.x); ffma2(acc[u][1], w2s, xA2.y);
            ffma2(acc[u][2], w2s, xB2.x); ffma2(acc[u][3], w2s, xB2.y);
            ffma2(acc[u][0], w3s, xA3.x); ffma2(acc[u][1], w3s, xA3.y);
            ffma2(acc[u][2], w3s, xB3.x); ffma2(acc[u][3], w3s, xB3.y);
        }
    }

    float* ob = g_t1 + b * DWc * HWp + pix0 + px0;
    #pragma unroll
    for (int u = 0; u < 8; ++u) {
        float bias = __ldg(&b1[oc0 + u]);
        float2 p0 = unpack2(acc[u][0]), p1 = unpack2(acc[u][1]);
        float2 p2 = unpack2(acc[u][2]), p3 = unpack2(acc[u][3]);
        float4 r0 = make_float4(p0.x + bias, p0.y + bias, p1.x + bias, p1.y + bias);
        float4 r1 = make_float4(p2.x + bias, p2.y + bias, p3.x + bias, p3.y + bias);
        *(float4*)(ob + (oc0 + u) * HWp)      = r0;
        *(float4*)(ob + (oc0 + u) * HWp + 64) = r1;
    }
}

// ---------------- K2: depthwise 3x3 + simple_gate + pool partials ----------------
__global__ void k2_kernel(const float* __restrict__ b2) {
    __shared__ float s0[6][258];
    __shared__ float s1[6][258];
    __shared__ float red[8];

    int b = blockIdx.z, c = blockIdx.y;
    int r0 = blockIdx.x * 4;
    int t = threadIdx.x;

    const float* t1a = g_t1 + (b * DWc + c) * HWp;
    const float* t1b = g_t1 + (b * DWc + c + 64) * HWp;

    if (t < 12) {
        int lr = t >> 1, col = (t & 1) ? 257 : 0;
        s0[lr][col] = 0.f;
        s1[lr][col] = 0.f;
    }
    #pragma unroll
    for (int lr = 0; lr < 6; ++lr) {
        int gr = r0 + lr - 1;
        bool ok = (gr >= 0 && gr < Hh);
        s0[lr][t + 1] = ok ? t1a[gr * Ww + t] : 0.f;
        s1[lr][t + 1] = ok ? t1b[gr * Ww + t] : 0.f;
    }
    __syncthreads();

    float wa[9], wb9[9];
    const float* w2a = g_w2 + (b * DWc + c) * 9;
    const float* w2b = g_w2 + (b * DWc + c + 64) * 9;
    #pragma unroll
    for (int i = 0; i < 9; ++i) { wa[i] = __ldg(&w2a[i]); wb9[i] = __ldg(&w2b[i]); }
    float biasA = __ldg(&b2[c]), biasB = __ldg(&b2[c + 64]);

    float* xgp = g_xg + (b * Cc + c) * HWp;
    float lsum = 0.f;
    int w = t;
    #pragma unroll
    for (int j = 0; j < 4; ++j) {
        float a0 = biasA, a1 = biasB;
        #pragma unroll
        for (int kh = 0; kh < 3; ++kh) {
            #pragma unroll
            for (int kw = 0; kw < 3; ++kw) {
                a0 += wa[kh * 3 + kw] * s0[j + kh][w + kw];
                a1 += wb9[kh * 3 + kw] * s1[j + kh][w + kw];
            }
        }
        float val = a0 * a1;
        xgp[(r0 + j) * Ww + w] = val;
        lsum += val;
    }

    #pragma unroll
    for (int o = 16; o > 0; o >>= 1)
        lsum += __shfl_xor_sync(0xffffffffu, lsum, o);
    if ((t & 31) == 0) red[t >> 5] = lsum;
    __syncthreads();
    if (t == 0) {
        float s = red[0] + red[1] + red[2] + red[3]
                + red[4] + red[5] + red[6] + red[7];
        g_part[(b * Cc + c) * 64 + blockIdx.x] = s;
    }
}

// ---------------- K4: fused tail on mma.sync bf16 (4-product split) ----------------
// grid (512, B), block 256.  CTA = 128 px; warp w owns the 16-px M-tile [w*16, w*16+16).
// A images (bf16 hi/lo) px-major stride AS=68 elems; y in fp32 smem stride 66.
#define AS 68
#define YS 66
#define OFF_AL  (128 * AS * 2)            // 17408
#define OFF_Y   (2 * 128 * AS * 2)        // 34816
#define OFF_MISC (OFF_Y + 128 * YS * 4)   // 68608
#define SM4_TOTAL (OFF_MISC + 2 * 64 * 4) // 69120

__global__ void __launch_bounds__(256, 2)
k4_kernel(const float* __restrict__ inp,
          const float* __restrict__ ln2w, const float* __restrict__ ln2b,
          const float* __restrict__ bsca,
          const float* __restrict__ b3, const float* __restrict__ b4,
          const float* __restrict__ b5,
          const float* __restrict__ beta, const float* __restrict__ gamma,
          float* __restrict__ out) {
    extern __shared__ char smem[];
    unsigned short* ah = (unsigned short*)smem;
    unsigned short* al = (unsigned short*)(smem + OFF_AL);
    float* ysm   = (float*)(smem + OFF_Y);
    float* s_pool = (float*)(smem + OFF_MISC);
    float* s_sca  = s_pool + 64;

    int t = threadIdx.x, wid = t >> 5, lane = t & 31;
    int g = lane >> 2, tt = lane & 3;
    int b = blockIdx.y, pix0 = blockIdx.x * 128;

    // pool mean + sca (k3 fold)
    if (t < 64) {
        float s = 0.f;
        const float4* pp = (const float4*)(g_part + (b * Cc + t) * 64);
        #pragma unroll
        for (int k = 0; k < 16; ++k) {
            float4 v = pp[k];
            s += (v.x + v.y) + (v.z + v.w);
        }
        s_pool[t] = s * (1.f / (float)HWp);
    }
    __syncthreads();
    if (t < 64) {
        const float* wr = g_wsca + b * Cc * Cc + t * Cc;
        float acc = __ldg(&bsca[t]);
        #pragma unroll
        for (int i = 0; i < 64; ++i) acc += wr[i] * s_pool[i];
        s_sca[t] = acc;
    }
    __syncthreads();

    // stage x = xg * sca into bf16 hi/lo A images (px-major)
    const float* xgb = g_xg + (size_t)(b * Cc) * HWp + pix0;
    #pragma unroll
    for (int it = 0; it < 32; ++it) {
        int idx = it * 256 + t;
        int c = idx >> 7, p = idx & 127;
        float v = xgb[(size_t)c * HWp + p] * s_sca[c];
        __nv_bfloat16 hh = __float2bfloat16(v);
        __nv_bfloat16 ll = __float2bfloat16(v - __bfloat162float(hh));
        ah[p * AS + c] = __bfloat16_as_ushort(hh);
        al[p * AS + c] = __bfloat16_as_ushort(ll);
    }
    __syncthreads();

    int rowg  = wid * 16 + g;
    int rowg8 = rowg + 8;
    const unsigned short* ahg  = ah + rowg  * AS;
    const unsigned short* ahg8 = ah + rowg8 * AS;
    const unsigned short* alg  = al + rowg  * AS;
    const unsigned short* alg8 = al + rowg8 * AS;

    // ---- mv1: conv3 (N=64, 8 tiles) ----
    float d1[8][4];
    #pragma unroll
    for (int j = 0; j < 8; ++j)
        #pragma unroll
        for (int i = 0; i < 4; ++i) d1[j][i] = 0.f;
    {
        const uint4* fb = g_f3 + b * 1024;
        #pragma unroll
        for (int ks = 0; ks < 4; ++ks) {
            int k0 = ks * 16 + 2 * tt;
            uint32_t ah0 = *(const uint32_t*)(ahg  + k0);
            uint32_t ah1 = *(const uint32_t*)(ahg8 + k0);
            uint32_t ah2 = *(const uint32_t*)(ahg  + k0 + 8);
            uint32_t ah3 = *(const uint32_t*)(ahg8 + k0 + 8);
            uint32_t al0 = *(const uint32_t*)(alg  + k0);
            uint32_t al1 = *(const uint32_t*)(alg8 + k0);
            uint32_t al2 = *(const uint32_t*)(alg  + k0 + 8);
            uint32_t al3 = *(const uint32_t*)(alg8 + k0 + 8);
            #pragma unroll
            for (int j = 0; j < 8; ++j) {
                uint4 f = __ldg(&fb[(j * 4 + ks) * 32 + lane]);
                mma_bf16(d1[j], ah0, ah1, ah2, ah3, f.x, f.y);
                mma_bf16(d1[j], ah0, ah1, ah2, ah3, f.z, f.w);
                mma_bf16(d1[j], al0, al1, al2, al3, f.x, f.y);
                mma_bf16(d1[j], al0, al1, al2, al3, f.z, f.w);
            }
        }
    }

    // ---- epilogue 1: y = inp + (d1 + b3)*beta ; LN2 stats ----
    float yA[16], yB[16];   // row g / row g+8, 16 channels each
    float sA = 0.f, qA = 0.f, sB = 0.f, qB = 0.f;
    {
        const float* ipn = inp + (size_t)(b * Cc) * HWp + pix0 + wid * 16;
        #pragma unroll
        for (int j = 0; j < 8; ++j) {
            #pragma unroll
            for (int e = 0; e < 2; ++e) {
                int c = 8 * j + 2 * tt + e;
                float bt = __ldg(&beta[c]), bi = __ldg(&b3[c]);
                float va = ipn[(size_t)c * HWp + g]     + (d1[j][e]     + bi) * bt;
                float vb = ipn[(size_t)c * HWp + g + 8] + (d1[j][2 + e] + bi) * bt;
                yA[j * 2 + e] = va; yB[j * 2 + e] = vb;
                sA += va; qA += va * va;
                sB += vb; qB += vb * vb;
            }
        }
        // reduce over the 4 lanes sharing each row (lane bits 0,1)
        #pragma unroll
        for (int o = 1; o <= 2; o <<= 1) {
            sA += __shfl_xor_sync(0xffffffffu, sA, o);
            qA += __shfl_xor_sync(0xffffffffu, qA, o);
            sB += __shfl_xor_sync(0xffffffffu, sB, o);
            qB += __shfl_xor_sync(0xffffffffu, qB, o);
        }
        float mA = sA * (1.f / 64.f), vA = qA * (1.f / 64.f) - mA * mA;
        float mB = sB * (1.f / 64.f), vB = qB * (1.f / 64.f) - mB * mB;
        float iA = rsqrtf(vA + EPSv), iB = rsqrtf(vB + EPSv);

        unsigned short* whg  = ah + rowg  * AS;
        unsigned short* whg8 = ah + rowg8 * AS;
        unsigned short* wlg  = al + rowg  * AS;
        unsigned short* wlg8 = al + rowg8 * AS;
        float* ysA = ysm + rowg  * YS;
        float* ysB = ysm + rowg8 * YS;
        #pragma unroll
        for (int j = 0; j < 8; ++j) {
            int c0 = 8 * j + 2 * tt;
            float w0 = __ldg(&ln2w[c0]),     w1 = __ldg(&ln2w[c0 + 1]);
            float o0 = __ldg(&ln2b[c0]),     o1 = __ldg(&ln2b[c0 + 1]);
            float zA0 = (yA[j * 2]     - mA) * iA * w0 + o0;
            float zA1 = (yA[j * 2 + 1] - mA) * iA * w1 + o1;
            float zB0 = (yB[j * 2]     - mB) * iB * w0 + o0;
            float zB1 = (yB[j * 2 + 1] - mB) * iB * w1 + o1;
            uint32_t hp, lp;
            split2(zA0, zA1, hp, lp);
            *(uint32_t*)(whg + c0) = hp;  *(uint32_t*)(wlg + c0) = lp;
            split2(zB0, zB1, hp, lp);
            *(uint32_t*)(whg8 + c0) = hp; *(uint32_t*)(wlg8 + c0) = lp;
            ysA[c0] = yA[j * 2]; ysA[c0 + 1] = yA[j * 2 + 1];
            ysB[c0] = yB[j * 2]; ysB[c0 + 1] = yB[j * 2 + 1];
        }
    }
    __syncwarp();

    // ---- mv2: conv4 (N=128, 16 tiles) ----
    float d2[16][4];
    #pragma unroll
    for (int j = 0; j < 16; ++j)
        #pragma unroll
        for (int i = 0; i < 4; ++i) d2[j][i] = 0.f;
    {
        const uint4* fb = g_f4 + b * 2048;
        #pragma unroll
        for (int ks = 0; ks < 4; ++ks) {
            int k0 = ks * 16 + 2 * tt;
            uint32_t ah0 = *(const uint32_t*)(ahg  + k0);
            uint32_t ah1 = *(const uint32_t*)(ahg8 + k0);
            uint32_t ah2 = *(const uint32_t*)(ahg  + k0 + 8);
            uint32_t ah3 = *(const uint32_t*)(ahg8 + k0 + 8);
            uint32_t al0 = *(const uint32_t*)(alg  + k0);
            uint32_t al1 = *(const uint32_t*)(alg8 + k0);
            uint32_t al2 = *(const uint32_t*)(alg  + k0 + 8);
            uint32_t al3 = *(const uint32_t*)(alg8 + k0 + 8);
            #pragma unroll
            for (int j = 0; j < 16; ++j) {
                uint4 f = __ldg(&fb[(j * 4 + ks) * 32 + lane]);
                mma_bf16(d2[j], ah0, ah1, ah2, ah3, f.x, f.y);
                mma_bf16(d2[j], ah0, ah1, ah2, ah3, f.z, f.w);
                mma_bf16(d2[j], al0, al1, al2, al3, f.x, f.y);
                mma_bf16(d2[j], al0, al1, al2, al3, f.z, f.w);
            }
        }
    }
    __syncwarp();

    // ---- gate: (d2[j]+b4[c]) * (d2[j+8]+b4[c+64]) -> A images ----
    {
        unsigned short* whg  = ah + rowg  * AS;
        unsigned short* whg8 = ah + rowg8 * AS;
        unsigned short* wlg  = al + rowg  * AS;
        unsigned short* wlg8 = al + rowg8 * AS;
        #pragma unroll
        for (int j = 0; j < 8; ++j) {
            int c0 = 8 * j + 2 * tt;
            float bl0 = __ldg(&b4[c0]),      bl1 = __ldg(&b4[c0 + 1]);
            float bh0 = __ldg(&b4[c0 + 64]), bh1 = __ldg(&b4[c0 + 65]);
            float gA0 = (d2[j][0] + bl0) * (d2[j + 8][0] + bh0);
            float gA1 = (d2[j][1] + bl1) * (d2[j + 8][1] + bh1);
            float gB0 = (d2[j][2] + bl0) * (d2[j + 8][2] + bh0);
            float gB1 = (d2[j][3] + bl1) * (d2[j + 8][3] + bh1);
            uint32_t hp, lp;
            split2(gA0, gA1, hp, lp);
            *(uint32_t*)(whg + c0) = hp;  *(uint32_t*)(wlg + c0) = lp;
            split2(gB0, gB1, hp, lp);
            *(uint32_t*)(whg8 + c0) = hp; *(uint32_t*)(wlg8 + c0) = lp;
        }
    }
    __syncwarp();

    // ---- mv3: conv5 (N=64, 8 tiles) ----
    float d3[8][4];
    #pragma unroll
    for (int j = 0; j < 8; ++j)
        #pragma unroll
        for (int i = 0; i < 4; ++i) d3[j][i] = 0.f;
    {
        const uint4* fb = g_f5 + b * 1024;
        #pragma unroll
        for (int ks = 0; ks < 4; ++ks) {
            int k0 = ks * 16 + 2 * tt;
            uint32_t ah0 = *(const uint32_t*)(ahg  + k0);
            uint32_t ah1 = *(const uint32_t*)(ahg8 + k0);
            uint32_t ah2 = *(const uint32_t*)(ahg  + k0 + 8);
            uint32_t ah3 = *(const uint32_t*)(ahg8 + k0 + 8);
            uint32_t al0 = *(const uint32_t*)(alg  + k0);
            uint32_t al1 = *(const uint32_t*)(alg8 + k0);
            uint32_t al2 = *(const uint32_t*)(alg  + k0 + 8);
            uint32_t al3 = *(const uint32_t*)(alg8 + k0 + 8);
            #pragma unroll
            for (int j = 0; j < 8; ++j) {
                uint4 f = __ldg(&fb[(j * 4 + ks) * 32 + lane]);
                mma_bf16(d3[j], ah0, ah1, ah2, ah3, f.x, f.y);
                mma_bf16(d3[j], ah0, ah1, ah2, ah3, f.z, f.w);
                mma_bf16(d3[j], al0, al1, al2, al3, f.x, f.y);
                mma_bf16(d3[j], al0, al1, al2, al3, f.z, f.w);
            }
        }
    }

    // ---- epilogue 3: out = y + (d3 + b5)*gamma ----
    {
        float* op = out + (size_t)(b * Cc) * HWp + pix0 + wid * 16;
        const float* ysA = ysm + rowg  * YS;
        const float* ysB = ysm + rowg8 * YS;
        #pragma unroll
        for (int j = 0; j < 8; ++j) {
            #pragma unroll
            for (int e = 0; e < 2; ++e) {
                int c = 8 * j + 2 * tt + e;
                float gm = __ldg(&gamma[c]), bi = __ldg(&b5[c]);
                op[(size_t)c * HWp + g]     = ysA[c] + (d3[j][e]     + bi) * gm;
                op[(size_t)c * HWp + g + 8] = ysB[c] + (d3[j][2 + e] + bi) * gm;
            }
        }
    }
}

// ---------------- launch ----------------
extern "C" void kernel_launch(void* const* d_in, const int* in_sizes, int n_in,
                              void* d_out, int out_size) {
    const float* inp   = (const float*)d_in[0];
    const float* probs = (const float*)d_in[1];
    const float* ln1w  = (const float*)d_in[2];
    const float* ln1b  = (const float*)d_in[3];
    const float* ln2w  = (const float*)d_in[4];
    const float* ln2b  = (const float*)d_in[5];
    const float* w1    = (const float*)d_in[6];
    const float* b1    = (const float*)d_in[7];
    const float* la1   = (const float*)d_in[8];
    const float* lb1   = (const float*)d_in[9];
    const float* w2    = (const float*)d_in[10];
    const float* b2    = (const float*)d_in[11];
    const float* la2   = (const float*)d_in[12];
    const float* lb2   = (const float*)d_in[13];
    const float* wsca  = (const float*)d_in[14];
    const float* bsca  = (const float*)d_in[15];
    const float* lasca = (const float*)d_in[16];
    const float* lbsca = (const float*)d_in[17];
    const float* w3    = (const float*)d_in[18];
    const float* b3    = (const float*)d_in[19];
    const float* la3   = (const float*)d_in[20];
    const float* lb3   = (const float*)d_in[21];
    const float* w4    = (const float*)d_in[22];
    const float* b4    = (const float*)d_in[23];
    const float* la4   = (const float*)d_in[24];
    const float* lb4   = (const float*)d_in[25];
    const float* w5    = (const float*)d_in[26];
    const float* b5    = (const float*)d_in[27];
    const float* la5   = (const float*)d_in[28];
    const float* lb5   = (const float*)d_in[29];
    const float* beta  = (const float*)d_in[30];
    const float* gamma = (const float*)d_in[31];
    float* out = (float*)d_out;

    cudaFuncSetAttribute(k4_kernel, cudaFuncAttributeMaxDynamicSharedMemorySize, SM4_TOTAL);

    k_weights<<<dim3(6, Bn), 256>>>(probs,
                                    w1, la1, lb1, w2, la2, lb2,
                                    wsca, lasca, lbsca, w3, la3, lb3,
                                    w4, la4, lb4, w5, la5, lb5);
    k1_kernel<<<dim3(HWp / 128, Bn), 256>>>(inp, ln1w, ln1b, b1);
    k2_kernel<<<dim3(Hh / 4, Cc, Bn), 256>>>(b2);
    k4_kernel<<<dim3(HWp / 128, Bn), 256, SM4_TOTAL>>>(inp, ln2w, ln2b, bsca, b3, b4, b5, beta, gamma, out);
}